// round 3
// baseline (speedup 1.0000x reference)
#include <cuda_runtime.h>
#include <math.h>

#define L 256
#define D 1024
#define H 16
#define DH 64

// ---------------- device scratch (no allocations allowed) ----------------
__device__ float g_Qm[L*D], g_Qv[L*D], g_Km[L*D], g_Kv[L*D], g_Vm[L*D], g_Vv[L*D];
__device__ float g_A [L*D];   // 0.5*(Qm^2 + Qv)
__device__ float g_F1[L*D];   // 1/Kv
__device__ float g_F2[L*D];   // Km/Kv
__device__ float g_Ck[H*L];   // per-(head,k) bias: sum_d 0.5*(Km^2/Kv + log Kv)
__device__ float g_Om[L*D], g_Ov[L*D];

// ---------------- f32x2 packed FMA helpers (sm_100+) ----------------
__device__ __forceinline__ unsigned long long pack2(float lo, float hi) {
    unsigned long long r;
    asm("mov.b64 %0, {%1, %2};" : "=l"(r) : "f"(lo), "f"(hi));
    return r;
}
__device__ __forceinline__ void unpack2(unsigned long long v, float& lo, float& hi) {
    asm("mov.b64 {%0, %1}, %2;" : "=f"(lo), "=f"(hi) : "l"(v));
}
__device__ __forceinline__ unsigned long long fma2(unsigned long long a,
                                                   unsigned long long b,
                                                   unsigned long long c) {
    unsigned long long d;
    asm("fma.rn.f32x2 %0, %1, %2, %3;" : "=l"(d) : "l"(a), "l"(b), "l"(c));
    return d;
}

__device__ __forceinline__ float softplusf(float x) {
    // logaddexp(x, 0) — overflow-safe, matches jax.nn.softplus
    return fmaxf(x, 0.0f) + log1pf(expf(-fabsf(x)));
}

// ---------------- 128x128 fp32 GEMM tile, f32x2 inner product ----------------
// C[row, col] = sum_k A[row,k] * W[k,col] + bias[col]   (M=256, N=K=D=1024)
__device__ __forceinline__ void sgemm_tile(
    const float* __restrict__ Am, const float* __restrict__ W,
    const float* __restrict__ bias, float* __restrict__ C,
    int bm, int bn, bool sp)
{
    __shared__ float As[2][16][132];  // [k][m], padded
    __shared__ float Bs[2][16][128];  // [k][n]
    const int tid = threadIdx.x;
    const int tx  = tid & 15, ty = tid >> 4;

    unsigned long long acc[8][4];
    #pragma unroll
    for (int i = 0; i < 8; i++)
        #pragma unroll
        for (int j = 0; j < 4; j++) acc[i][j] = 0ull;

    float4 ar[2], br[2];
    auto LDG = [&](int kt) {
        #pragma unroll
        for (int u = 0; u < 2; u++) {
            int idx  = tid + u * 256;
            int arow = idx >> 2, ak = (idx & 3) << 2;
            ar[u] = *(const float4*)(Am + (bm + arow) * D + kt + ak);
            int brow = idx >> 5, bc = (idx & 31) << 2;
            br[u] = *(const float4*)(W + (kt + brow) * D + bn + bc);
        }
    };
    auto STS = [&](int buf) {
        #pragma unroll
        for (int u = 0; u < 2; u++) {
            int idx  = tid + u * 256;
            int arow = idx >> 2, ak = (idx & 3) << 2;
            As[buf][ak + 0][arow] = ar[u].x;
            As[buf][ak + 1][arow] = ar[u].y;
            As[buf][ak + 2][arow] = ar[u].z;
            As[buf][ak + 3][arow] = ar[u].w;
            int brow = idx >> 5, bc = (idx & 31) << 2;
            *(float4*)&Bs[buf][brow][bc] = br[u];
        }
    };

    LDG(0); STS(0); __syncthreads();
    const int NK = D / 16;
    for (int t = 0; t < NK; t++) {
        int cur = t & 1;
        if (t + 1 < NK) LDG((t + 1) * 16);
        #pragma unroll
        for (int k = 0; k < 16; k++) {
            float4 aL = *(const float4*)&As[cur][k][ty * 4];
            float4 aH = *(const float4*)&As[cur][k][64 + ty * 4];
            float4 bL = *(const float4*)&Bs[cur][k][tx * 4];
            float4 bH = *(const float4*)&Bs[cur][k][64 + tx * 4];
            unsigned long long b2[4] = { pack2(bL.x, bL.y), pack2(bL.z, bL.w),
                                         pack2(bH.x, bH.y), pack2(bH.z, bH.w) };
            float av[8] = { aL.x, aL.y, aL.z, aL.w, aH.x, aH.y, aH.z, aH.w };
            #pragma unroll
            for (int i = 0; i < 8; i++) {
                unsigned long long a2 = pack2(av[i], av[i]);
                #pragma unroll
                for (int j = 0; j < 4; j++) acc[i][j] = fma2(a2, b2[j], acc[i][j]);
            }
        }
        if (t + 1 < NK) STS(cur ^ 1);
        __syncthreads();
    }

    #pragma unroll
    for (int i = 0; i < 8; i++) {
        int row = bm + ((i < 4) ? (ty * 4 + i) : (64 + ty * 4 + (i - 4)));
        #pragma unroll
        for (int j = 0; j < 4; j++) {
            int col = bn + ((j < 2) ? (tx * 4 + j * 2) : (64 + tx * 4 + (j - 2) * 2));
            float lo, hi; unpack2(acc[i][j], lo, hi);
            lo += bias[col]; hi += bias[col + 1];
            if (sp) { lo = softplusf(lo); hi = softplusf(hi); }
            *(float2*)(C + row * D + col) = make_float2(lo, hi);
        }
    }
}

// ---------------- kernel 1: six QKV GEMMs ----------------
__global__ __launch_bounds__(256) void qkv_gemm_kernel(
    const float* mu, const float* var,
    const float* wqm, const float* bqm, const float* wqv, const float* bqv,
    const float* wkm, const float* bkm, const float* wkv, const float* bkv,
    const float* wvm, const float* bvm, const float* wvv, const float* bvv)
{
    const float* A; const float* W; const float* b; float* C; bool sp;
    switch (blockIdx.z) {
        case 0:  A = mu;  W = wqm; b = bqm; C = g_Qm; sp = false; break;
        case 1:  A = var; W = wqv; b = bqv; C = g_Qv; sp = true;  break;
        case 2:  A = mu;  W = wkm; b = bkm; C = g_Km; sp = false; break;
        case 3:  A = var; W = wkv; b = bkv; C = g_Kv; sp = true;  break;
        case 4:  A = mu;  W = wvm; b = bvm; C = g_Vm; sp = false; break;
        default: A = var; W = wvv; b = bvv; C = g_Vv; sp = true;  break;
    }
    sgemm_tile(A, W, b, C, blockIdx.y * 128, blockIdx.x * 128, sp);
}

// ---------------- kernel 2: elementwise features + per-k bias ----------------
__global__ __launch_bounds__(256) void prep_kernel()
{
    int tid = blockIdx.x * 256 + threadIdx.x;   // 0..131071, 2 elems each
    int e0  = tid * 2;
    float c = 0.0f;
    #pragma unroll
    for (int u = 0; u < 2; u++) {
        int e = e0 + u;
        float qm = g_Qm[e], qv = g_Qv[e];
        g_A[e] = 0.5f * (qm * qm + qv);
        float kv  = g_Kv[e];
        float inv = 1.0f / kv;
        float km  = g_Km[e];
        g_F1[e] = inv;
        g_F2[e] = km * inv;
        c += 0.5f * (km * km * inv + logf(kv));
    }
    // one warp == one (row, head) group of 64 elements
    #pragma unroll
    for (int off = 16; off; off >>= 1) c += __shfl_xor_sync(0xffffffffu, c, off);
    if ((threadIdx.x & 31) == 0) {
        int w = tid >> 5;
        int row = w >> 4, h = w & 15;
        g_Ck[h * L + row] = c;
    }
}

// ---------------- kernel 3: fused attention per (q-tile-64, head) ----------------
// smem layout (floats):
//   phase 1: sAq[64][65] @0, sQm[64][65] @4160, sF1t[64][257] @8320,
//            sF2t[64][257] @24768, sCk[256] @41216
//   phase 2: sVm[64][64] @0, sVv[64][64] @4096, sP[256][65] @8320, sP2[256][65] @24960
#define ATTN_SMEM_FLOATS 41600
#define O_AQ 0
#define O_QM 4160
#define O_F1 8320
#define O_F2 24768
#define O_CK 41216
#define O_VM 0
#define O_VV 4096
#define O_P  8320
#define O_P2 24960

__global__ __launch_bounds__(256) void attn_kernel()
{
    extern __shared__ float sm[];
    const int h  = blockIdx.y;
    const int q0 = blockIdx.x * 64;
    const int tid = threadIdx.x;
    const int tx = tid & 15, ty = tid >> 4;

    // ---- load q-side ([d][q], folded signs), k-side features ([d][k]) ----
    #pragma unroll
    for (int u = 0; u < 4; u++) {
        int idx = tid + u * 256;                 // 0..1023
        int q = idx >> 4, d4 = (idx & 15) << 2;
        float4 a = *(const float4*)(g_A  + (q0 + q) * D + h * DH + d4);
        float4 m = *(const float4*)(g_Qm + (q0 + q) * D + h * DH + d4);
        sm[O_AQ + (d4 + 0) * 65 + q] = a.x;
        sm[O_AQ + (d4 + 1) * 65 + q] = a.y;
        sm[O_AQ + (d4 + 2) * 65 + q] = a.z;
        sm[O_AQ + (d4 + 3) * 65 + q] = a.w;
        sm[O_QM + (d4 + 0) * 65 + q] = -m.x;
        sm[O_QM + (d4 + 1) * 65 + q] = -m.y;
        sm[O_QM + (d4 + 2) * 65 + q] = -m.z;
        sm[O_QM + (d4 + 3) * 65 + q] = -m.w;
    }
    #pragma unroll
    for (int u = 0; u < 16; u++) {
        int idx = tid + u * 256;                 // 0..4095
        int k = idx >> 4, d4 = (idx & 15) << 2;
        float4 f1 = *(const float4*)(g_F1 + k * D + h * DH + d4);
        float4 f2 = *(const float4*)(g_F2 + k * D + h * DH + d4);
        sm[O_F1 + (d4 + 0) * 257 + k] = f1.x;
        sm[O_F1 + (d4 + 1) * 257 + k] = f1.y;
        sm[O_F1 + (d4 + 2) * 257 + k] = f1.z;
        sm[O_F1 + (d4 + 3) * 257 + k] = f1.w;
        sm[O_F2 + (d4 + 0) * 257 + k] = f2.x;
        sm[O_F2 + (d4 + 1) * 257 + k] = f2.y;
        sm[O_F2 + (d4 + 2) * 257 + k] = f2.z;
        sm[O_F2 + (d4 + 3) * 257 + k] = f2.w;
    }
    if (tid < 256) sm[O_CK + tid] = g_Ck[h * L + tid];
    __syncthreads();

    // ---- scores: s[q, k] = 0.5*A.F1 - Qm.F2 (signs folded into smem) ----
    float s[4][16];
    #pragma unroll
    for (int i = 0; i < 4; i++)
        #pragma unroll
        for (int j = 0; j < 16; j++) s[i][j] = 0.0f;

    #pragma unroll 4
    for (int d = 0; d < 64; d++) {
        float a[4], qn[4];
        #pragma unroll
        for (int i = 0; i < 4; i++) {
            a[i]  = sm[O_AQ + d * 65 + ty * 4 + i];
            qn[i] = sm[O_QM + d * 65 + ty * 4 + i];
        }
        #pragma unroll
        for (int j = 0; j < 16; j++) {
            float f1 = sm[O_F1 + d * 257 + j * 16 + tx];
            float f2 = sm[O_F2 + d * 257 + j * 16 + tx];
            #pragma unroll
            for (int i = 0; i < 4; i++)
                s[i][j] += a[i] * f1 + qn[i] * f2;
        }
    }

    // add per-k bias, scale: score = -(kl)/8.  per-q terms cancel in softmax.
    #pragma unroll
    for (int j = 0; j < 16; j++) {
        float ck = sm[O_CK + j * 16 + tx];
        #pragma unroll
        for (int i = 0; i < 4; i++)
            s[i][j] = -0.125f * (s[i][j] + ck);
    }

    // ---- softmax over k (16 lanes x 16 regs per row) ----
    float rinv[4];
    #pragma unroll
    for (int i = 0; i < 4; i++) {
        float m = s[i][0];
        #pragma unroll
        for (int j = 1; j < 16; j++) m = fmaxf(m, s[i][j]);
        #pragma unroll
        for (int off = 8; off; off >>= 1)
            m = fmaxf(m, __shfl_xor_sync(0xffffffffu, m, off));
        float sum = 0.0f;
        #pragma unroll
        for (int j = 0; j < 16; j++) {
            float e = __expf(s[i][j] - m);
            s[i][j] = e;
            sum += e;
        }
        #pragma unroll
        for (int off = 8; off; off >>= 1)
            sum += __shfl_xor_sync(0xffffffffu, sum, off);
        rinv[i] = 1.0f / sum;
    }

    __syncthreads();   // all phase-1 smem reads complete

    // ---- write normalized attn and attn^2 ([k][q], padded 65) ----
    #pragma unroll
    for (int j = 0; j < 16; j++) {
        int k = j * 16 + tx;
        #pragma unroll
        for (int i = 0; i < 4; i++) {
            int q = ty * 4 + i;
            float pn = s[i][j] * rinv[i];
            sm[O_P  + k * 65 + q] = pn;
            sm[O_P2 + k * 65 + q] = pn * pn;
        }
    }

    // ---- PV: out = attn @ Vm, attn^2 @ Vv  (k-chunks of 64) ----
    float om[4][4], ov[4][4];
    #pragma unroll
    for (int i = 0; i < 4; i++)
        #pragma unroll
        for (int r = 0; r < 4; r++) { om[i][r] = 0.0f; ov[i][r] = 0.0f; }

    for (int kb = 0; kb < 4; kb++) {
        #pragma unroll
        for (int u = 0; u < 4; u++) {
            int idx = tid + u * 256;
            int r = idx >> 4, d4 = (idx & 15) << 2;
            *(float4*)&sm[O_VM + r * 64 + d4] =
                *(const float4*)(g_Vm + (kb * 64 + r) * D + h * DH + d4);
            *(float4*)&sm[O_VV + r * 64 + d4] =
                *(const float4*)(g_Vv + (kb * 64 + r) * D + h * DH + d4);
        }
        __syncthreads();
        #pragma unroll 4
        for (int kk = 0; kk < 64; kk++) {
            int k = kb * 64 + kk;
            float pm[4], pv[4];
            #pragma unroll
            for (int i = 0; i < 4; i++) {
                pm[i] = sm[O_P  + k * 65 + ty * 4 + i];
                pv[i] = sm[O_P2 + k * 65 + ty * 4 + i];
            }
            float4 vm = *(const float4*)&sm[O_VM + kk * 64 + tx * 4];
            float4 vv = *(const float4*)&sm[O_VV + kk * 64 + tx * 4];
            #pragma unroll
            for (int i = 0; i < 4; i++) {
                om[i][0] += pm[i] * vm.x; om[i][1] += pm[i] * vm.y;
                om[i][2] += pm[i] * vm.z; om[i][3] += pm[i] * vm.w;
                ov[i][0] += pv[i] * vv.x; ov[i][1] += pv[i] * vv.y;
                ov[i][2] += pv[i] * vv.z; ov[i][3] += pv[i] * vv.w;
            }
        }
        if (kb < 3) __syncthreads();
    }

    #pragma unroll
    for (int i = 0; i < 4; i++) {
        int q = q0 + ty * 4 + i;
        *(float4*)(g_Om + q * D + h * DH + tx * 4) =
            make_float4(om[i][0], om[i][1], om[i][2], om[i][3]);
        *(float4*)(g_Ov + q * D + h * DH + tx * 4) =
            make_float4(ov[i][0], ov[i][1], ov[i][2], ov[i][3]);
    }
}

// ---------------- kernel 4: output GEMMs ----------------
__global__ __launch_bounds__(256) void out_gemm_kernel(
    const float* wom, const float* bom, const float* wov, const float* bov,
    float* out)
{
    int bm = blockIdx.y * 128, bn = blockIdx.x * 128;
    if (blockIdx.z == 0)
        sgemm_tile(g_Om, wom, bom, out, bm, bn, false);
    else
        sgemm_tile(g_Ov, wov, bov, out + L * D, bm, bn, true);
}

// ---------------- launch ----------------
extern "C" void kernel_launch(void* const* d_in, const int* in_sizes, int n_in,
                              void* d_out, int out_size)
{
    const float* mu  = (const float*)d_in[0];
    const float* var = (const float*)d_in[1];
    const float* wqm = (const float*)d_in[2],  * bqm = (const float*)d_in[3];
    const float* wqv = (const float*)d_in[4],  * bqv = (const float*)d_in[5];
    const float* wkm = (const float*)d_in[6],  * bkm = (const float*)d_in[7];
    const float* wkv = (const float*)d_in[8],  * bkv = (const float*)d_in[9];
    const float* wvm = (const float*)d_in[10], * bvm = (const float*)d_in[11];
    const float* wvv = (const float*)d_in[12], * bvv = (const float*)d_in[13];
    const float* wom = (const float*)d_in[14], * bom = (const float*)d_in[15];
    const float* wov = (const float*)d_in[16], * bov = (const float*)d_in[17];
    float* out = (float*)d_out;

    cudaFuncSetAttribute(attn_kernel, cudaFuncAttributeMaxDynamicSharedMemorySize,
                         ATTN_SMEM_FLOATS * 4);

    dim3 g1(8, 2, 6);
    qkv_gemm_kernel<<<g1, 256>>>(mu, var, wqm, bqm, wqv, bqv,
                                 wkm, bkm, wkv, bkv, wvm, bvm, wvv, bvv);
    prep_kernel<<<512, 256>>>();
    attn_kernel<<<dim3(4, 16), 256, ATTN_SMEM_FLOATS * 4>>>();
    dim3 g2(8, 2, 2);
    out_gemm_kernel<<<g2, 256>>>(wom, bom, wov, bov, out);
}

// round 4
// speedup vs baseline: 1.6158x; 1.6158x over previous
#include <cuda_runtime.h>
#include <math.h>

#define L 256
#define D 1024
#define H 16
#define DH 64
#define LD (L*D)

// ---------------- device scratch (no allocations allowed) ----------------
__device__ float g_Qm[LD], g_Vm[LD], g_Vv[LD];
__device__ float g_A [LD];   // 0.5*(Qm^2 + Qv)
__device__ float g_F1[LD];   // 1/Kv
__device__ float g_F2[LD];   // Km/Kv
__device__ float g_Ck[H*L];  // per-(head,k) bias
__device__ float g_Om[LD], g_Ov[LD];
// split-K partial buffers
__device__ float g_qkv_part[3*6*LD];   // [split][gemm][L*D]
__device__ float g_out_part[8*2*LD];   // [split][gemm][L*D]

// ---------------- f32x2 packed FMA helpers (sm_100+) ----------------
__device__ __forceinline__ unsigned long long pack2(float lo, float hi) {
    unsigned long long r;
    asm("mov.b64 %0, {%1, %2};" : "=l"(r) : "f"(lo), "f"(hi));
    return r;
}
__device__ __forceinline__ void unpack2(unsigned long long v, float& lo, float& hi) {
    asm("mov.b64 {%0, %1}, %2;" : "=f"(lo), "=f"(hi) : "l"(v));
}
__device__ __forceinline__ unsigned long long fma2(unsigned long long a,
                                                   unsigned long long b,
                                                   unsigned long long c) {
    unsigned long long d;
    asm("fma.rn.f32x2 %0, %1, %2, %3;" : "=l"(d) : "l"(a), "l"(b), "l"(c));
    return d;
}

__device__ __forceinline__ float softplusf(float x) {
    return fmaxf(x, 0.0f) + log1pf(expf(-fabsf(x)));
}

// ---------------- 128x128 fp32 GEMM tile over K range, f32x2 inner product --
// Cpart[row, col] = sum_{k in [k0, k0+nk16*16)} A[row,k] * W[k,col]
__device__ __forceinline__ void sgemm_tile_partial(
    const float* __restrict__ Am, const float* __restrict__ W,
    float* __restrict__ Cpart, int bm, int bn, int k0, int nk16)
{
    __shared__ float As[2][16][132];  // [k][m], padded
    __shared__ float Bs[2][16][128];  // [k][n]
    const int tid = threadIdx.x;
    const int tx  = tid & 15, ty = tid >> 4;

    unsigned long long acc[8][4];
    #pragma unroll
    for (int i = 0; i < 8; i++)
        #pragma unroll
        for (int j = 0; j < 4; j++) acc[i][j] = 0ull;

    float4 ar[2], br[2];
    auto LDG = [&](int kt) {
        #pragma unroll
        for (int u = 0; u < 2; u++) {
            int idx  = tid + u * 256;
            int arow = idx >> 2, ak = (idx & 3) << 2;
            ar[u] = *(const float4*)(Am + (bm + arow) * D + k0 + kt + ak);
            int brow = idx >> 5, bc = (idx & 31) << 2;
            br[u] = *(const float4*)(W + (k0 + kt + brow) * D + bn + bc);
        }
    };
    auto STS = [&](int buf) {
        #pragma unroll
        for (int u = 0; u < 2; u++) {
            int idx  = tid + u * 256;
            int arow = idx >> 2, ak = (idx & 3) << 2;
            As[buf][ak + 0][arow] = ar[u].x;
            As[buf][ak + 1][arow] = ar[u].y;
            As[buf][ak + 2][arow] = ar[u].z;
            As[buf][ak + 3][arow] = ar[u].w;
            int brow = idx >> 5, bc = (idx & 31) << 2;
            *(float4*)&Bs[buf][brow][bc] = br[u];
        }
    };

    LDG(0); STS(0); __syncthreads();
    for (int t = 0; t < nk16; t++) {
        int cur = t & 1;
        if (t + 1 < nk16) LDG((t + 1) * 16);
        #pragma unroll
        for (int k = 0; k < 16; k++) {
            float4 aL = *(const float4*)&As[cur][k][ty * 4];
            float4 aH = *(const float4*)&As[cur][k][64 + ty * 4];
            float4 bL = *(const float4*)&Bs[cur][k][tx * 4];
            float4 bH = *(const float4*)&Bs[cur][k][64 + tx * 4];
            unsigned long long b2[4] = { pack2(bL.x, bL.y), pack2(bL.z, bL.w),
                                         pack2(bH.x, bH.y), pack2(bH.z, bH.w) };
            float av[8] = { aL.x, aL.y, aL.z, aL.w, aH.x, aH.y, aH.z, aH.w };
            #pragma unroll
            for (int i = 0; i < 8; i++) {
                unsigned long long a2 = pack2(av[i], av[i]);
                #pragma unroll
                for (int j = 0; j < 4; j++) acc[i][j] = fma2(a2, b2[j], acc[i][j]);
            }
        }
        if (t + 1 < nk16) STS(cur ^ 1);
        __syncthreads();
    }

    #pragma unroll
    for (int i = 0; i < 8; i++) {
        int row = bm + ((i < 4) ? (ty * 4 + i) : (64 + ty * 4 + (i - 4)));
        #pragma unroll
        for (int j = 0; j < 4; j++) {
            int col = bn + ((j < 2) ? (tx * 4 + j * 2) : (64 + tx * 4 + (j - 2) * 2));
            float lo, hi; unpack2(acc[i][j], lo, hi);
            *(float2*)(Cpart + row * D + col) = make_float2(lo, hi);
        }
    }
}

// ---------------- kernel 1: six QKV GEMMs, split-K 3 (288 CTAs) -------------
__global__ __launch_bounds__(256, 2) void qkv_gemm_kernel(
    const float* mu, const float* var,
    const float* wqm, const float* wqv,
    const float* wkm, const float* wkv,
    const float* wvm, const float* wvv)
{
    int g = blockIdx.z / 3, s = blockIdx.z % 3;
    const float* A; const float* W;
    switch (g) {
        case 0:  A = mu;  W = wqm; break;
        case 1:  A = var; W = wqv; break;
        case 2:  A = mu;  W = wkm; break;
        case 3:  A = var; W = wkv; break;
        case 4:  A = mu;  W = wvm; break;
        default: A = var; W = wvv; break;
    }
    int k0   = (s == 0) ? 0   : (s == 1) ? 352 : 688;
    int nk16 = (s == 0) ? 22  : 21;
    sgemm_tile_partial(A, W, g_qkv_part + (s * 6 + g) * LD,
                       blockIdx.y * 128, blockIdx.x * 128, k0, nk16);
}

// ---------------- kernel 2: QKV epilogue (split sum + bias + act) + prep ----
__global__ __launch_bounds__(256) void prep_kernel(
    const float* bqm, const float* bqv, const float* bkm, const float* bkv,
    const float* bvm, const float* bvv)
{
    int tid = blockIdx.x * 256 + threadIdx.x;   // 0..131071, 2 elems each
    int e0  = tid * 2;
    float c = 0.0f;
    float2 v[6];
    #pragma unroll
    for (int g = 0; g < 6; g++) {
        float2 p0 = *(const float2*)(g_qkv_part + (0 * 6 + g) * LD + e0);
        float2 p1 = *(const float2*)(g_qkv_part + (1 * 6 + g) * LD + e0);
        float2 p2 = *(const float2*)(g_qkv_part + (2 * 6 + g) * LD + e0);
        v[g] = make_float2(p0.x + p1.x + p2.x, p0.y + p1.y + p2.y);
    }
    int col = e0 & (D - 1);
    float vals[6][2] = {
        { v[0].x + bqm[col], v[0].y + bqm[col + 1] },
        { v[1].x + bqv[col], v[1].y + bqv[col + 1] },
        { v[2].x + bkm[col], v[2].y + bkm[col + 1] },
        { v[3].x + bkv[col], v[3].y + bkv[col + 1] },
        { v[4].x + bvm[col], v[4].y + bvm[col + 1] },
        { v[5].x + bvv[col], v[5].y + bvv[col + 1] },
    };
    float qm2[2], a2v[2], f1v[2], f2v[2], vv2[2];
    #pragma unroll
    for (int u = 0; u < 2; u++) {
        float qm = vals[0][u];
        float qv = softplusf(vals[1][u]);
        float km = vals[2][u];
        float kv = softplusf(vals[3][u]);
        float inv = 1.0f / kv;
        qm2[u] = qm;
        a2v[u] = 0.5f * (qm * qm + qv);
        f1v[u] = inv;
        f2v[u] = km * inv;
        vv2[u] = softplusf(vals[5][u]);
        c += 0.5f * (km * km * inv + logf(kv));
    }
    *(float2*)(g_Qm + e0) = make_float2(qm2[0], qm2[1]);
    *(float2*)(g_A  + e0) = make_float2(a2v[0], a2v[1]);
    *(float2*)(g_F1 + e0) = make_float2(f1v[0], f1v[1]);
    *(float2*)(g_F2 + e0) = make_float2(f2v[0], f2v[1]);
    *(float2*)(g_Vm + e0) = make_float2(vals[4][0], vals[4][1]);
    *(float2*)(g_Vv + e0) = make_float2(vv2[0], vv2[1]);

    // one warp == one (row, head) group of 64 elements
    #pragma unroll
    for (int off = 16; off; off >>= 1) c += __shfl_xor_sync(0xffffffffu, c, off);
    if ((threadIdx.x & 31) == 0) {
        int w = tid >> 5;
        int row = w >> 4, h = w & 15;
        g_Ck[h * L + row] = c;
    }
}

// ---------------- kernel 3: fused attention per (q-tile-32, head) -----------
// smem floats:
//  phase 1: sAq[64][33]@0, sQm[64][33]@2112, sF1[64][257]@4224,
//           sF2[64][257]@20672, sCk[256]@37120  -> total 37376
//  phase 2: sVm[64][64]@0, sVv[64][64]@4096, sP[256][33]@8192, sP2[256][33]@16640
#define ATTN_SMEM_FLOATS 37376
#define O_AQ 0
#define O_QM 2112
#define O_F1 4224
#define O_F2 20672
#define O_CK 37120
#define O_VM 0
#define O_VV 4096
#define O_P  8192
#define O_P2 16640

__global__ __launch_bounds__(256) void attn_kernel()
{
    extern __shared__ float sm[];
    const int h  = blockIdx.y;
    const int q0 = blockIdx.x * 32;
    const int tid = threadIdx.x;
    const int tx = tid & 15, ty = tid >> 4;

    // q-side ([d][q], signs folded)
    #pragma unroll
    for (int u = 0; u < 2; u++) {
        int idx = tid + u * 256;                 // 0..511
        int q = idx >> 4, d4 = (idx & 15) << 2;
        float4 a = *(const float4*)(g_A  + (q0 + q) * D + h * DH + d4);
        float4 m = *(const float4*)(g_Qm + (q0 + q) * D + h * DH + d4);
        sm[O_AQ + (d4 + 0) * 33 + q] = a.x;
        sm[O_AQ + (d4 + 1) * 33 + q] = a.y;
        sm[O_AQ + (d4 + 2) * 33 + q] = a.z;
        sm[O_AQ + (d4 + 3) * 33 + q] = a.w;
        sm[O_QM + (d4 + 0) * 33 + q] = -m.x;
        sm[O_QM + (d4 + 1) * 33 + q] = -m.y;
        sm[O_QM + (d4 + 2) * 33 + q] = -m.z;
        sm[O_QM + (d4 + 3) * 33 + q] = -m.w;
    }
    // k-side features ([d][k])
    #pragma unroll
    for (int u = 0; u < 16; u++) {
        int idx = tid + u * 256;                 // 0..4095
        int k = idx >> 4, d4 = (idx & 15) << 2;
        float4 f1 = *(const float4*)(g_F1 + k * D + h * DH + d4);
        float4 f2 = *(const float4*)(g_F2 + k * D + h * DH + d4);
        sm[O_F1 + (d4 + 0) * 257 + k] = f1.x;
        sm[O_F1 + (d4 + 1) * 257 + k] = f1.y;
        sm[O_F1 + (d4 + 2) * 257 + k] = f1.z;
        sm[O_F1 + (d4 + 3) * 257 + k] = f1.w;
        sm[O_F2 + (d4 + 0) * 257 + k] = f2.x;
        sm[O_F2 + (d4 + 1) * 257 + k] = f2.y;
        sm[O_F2 + (d4 + 2) * 257 + k] = f2.z;
        sm[O_F2 + (d4 + 3) * 257 + k] = f2.w;
    }
    if (tid < 256) sm[O_CK + tid] = g_Ck[h * L + tid];
    __syncthreads();

    // scores: s[q, k] = 0.5*A.F1 - Qm.F2 (signs folded into smem)
    float s[2][16];
    #pragma unroll
    for (int i = 0; i < 2; i++)
        #pragma unroll
        for (int j = 0; j < 16; j++) s[i][j] = 0.0f;

    #pragma unroll 4
    for (int d = 0; d < 64; d++) {
        float a[2], qn[2];
        #pragma unroll
        for (int i = 0; i < 2; i++) {
            a[i]  = sm[O_AQ + d * 33 + ty * 2 + i];
            qn[i] = sm[O_QM + d * 33 + ty * 2 + i];
        }
        #pragma unroll
        for (int j = 0; j < 16; j++) {
            float f1 = sm[O_F1 + d * 257 + j * 16 + tx];
            float f2 = sm[O_F2 + d * 257 + j * 16 + tx];
            #pragma unroll
            for (int i = 0; i < 2; i++)
                s[i][j] += a[i] * f1 + qn[i] * f2;
        }
    }

    #pragma unroll
    for (int j = 0; j < 16; j++) {
        float ck = sm[O_CK + j * 16 + tx];
        #pragma unroll
        for (int i = 0; i < 2; i++)
            s[i][j] = -0.125f * (s[i][j] + ck);
    }

    // softmax over k
    float rinv[2];
    #pragma unroll
    for (int i = 0; i < 2; i++) {
        float m = s[i][0];
        #pragma unroll
        for (int j = 1; j < 16; j++) m = fmaxf(m, s[i][j]);
        #pragma unroll
        for (int off = 8; off; off >>= 1)
            m = fmaxf(m, __shfl_xor_sync(0xffffffffu, m, off));
        float sum = 0.0f;
        #pragma unroll
        for (int j = 0; j < 16; j++) {
            float e = __expf(s[i][j] - m);
            s[i][j] = e;
            sum += e;
        }
        #pragma unroll
        for (int off = 8; off; off >>= 1)
            sum += __shfl_xor_sync(0xffffffffu, sum, off);
        rinv[i] = 1.0f / sum;
    }

    __syncthreads();   // all phase-1 smem reads complete

    #pragma unroll
    for (int j = 0; j < 16; j++) {
        int k = j * 16 + tx;
        #pragma unroll
        for (int i = 0; i < 2; i++) {
            int q = ty * 2 + i;
            float pn = s[i][j] * rinv[i];
            sm[O_P  + k * 33 + q] = pn;
            sm[O_P2 + k * 33 + q] = pn * pn;
        }
    }

    // PV: out = attn @ Vm, attn^2 @ Vv  (k-chunks of 64)
    float om[2][4], ov[2][4];
    #pragma unroll
    for (int i = 0; i < 2; i++)
        #pragma unroll
        for (int r = 0; r < 4; r++) { om[i][r] = 0.0f; ov[i][r] = 0.0f; }

    for (int kb = 0; kb < 4; kb++) {
        #pragma unroll
        for (int u = 0; u < 4; u++) {
            int idx = tid + u * 256;
            int r = idx >> 4, d4 = (idx & 15) << 2;
            *(float4*)&sm[O_VM + r * 64 + d4] =
                *(const float4*)(g_Vm + (kb * 64 + r) * D + h * DH + d4);
            *(float4*)&sm[O_VV + r * 64 + d4] =
                *(const float4*)(g_Vv + (kb * 64 + r) * D + h * DH + d4);
        }
        __syncthreads();
        #pragma unroll 4
        for (int kk = 0; kk < 64; kk++) {
            int k = kb * 64 + kk;
            float pm[2], pv[2];
            #pragma unroll
            for (int i = 0; i < 2; i++) {
                pm[i] = sm[O_P  + k * 33 + ty * 2 + i];
                pv[i] = sm[O_P2 + k * 33 + ty * 2 + i];
            }
            float4 vm = *(const float4*)&sm[O_VM + kk * 64 + tx * 4];
            float4 vv = *(const float4*)&sm[O_VV + kk * 64 + tx * 4];
            #pragma unroll
            for (int i = 0; i < 2; i++) {
                om[i][0] += pm[i] * vm.x; om[i][1] += pm[i] * vm.y;
                om[i][2] += pm[i] * vm.z; om[i][3] += pm[i] * vm.w;
                ov[i][0] += pv[i] * vv.x; ov[i][1] += pv[i] * vv.y;
                ov[i][2] += pv[i] * vv.z; ov[i][3] += pv[i] * vv.w;
            }
        }
        if (kb < 3) __syncthreads();
    }

    #pragma unroll
    for (int i = 0; i < 2; i++) {
        int q = q0 + ty * 2 + i;
        *(float4*)(g_Om + q * D + h * DH + tx * 4) =
            make_float4(om[i][0], om[i][1], om[i][2], om[i][3]);
        *(float4*)(g_Ov + q * D + h * DH + tx * 4) =
            make_float4(ov[i][0], ov[i][1], ov[i][2], ov[i][3]);
    }
}

// ---------------- kernel 4: output GEMMs, split-K 8 (256 CTAs) --------------
__global__ __launch_bounds__(256, 2) void out_gemm_kernel(
    const float* wom, const float* wov)
{
    int g = blockIdx.z & 1, s = blockIdx.z >> 1;
    const float* A = g ? g_Ov : g_Om;
    const float* W = g ? wov  : wom;
    sgemm_tile_partial(A, W, g_out_part + (s * 2 + g) * LD,
                       blockIdx.y * 128, blockIdx.x * 128, s * 128, 8);
}

// ---------------- kernel 5: output epilogue ----------------
__global__ __launch_bounds__(256) void out_epilogue_kernel(
    const float* bom, const float* bov, float* out)
{
    int g = blockIdx.y;
    int e = (blockIdx.x * 256 + threadIdx.x) * 4;   // 0..LD-4
    float4 acc = make_float4(0.f, 0.f, 0.f, 0.f);
    #pragma unroll
    for (int s = 0; s < 8; s++) {
        float4 p = *(const float4*)(g_out_part + (s * 2 + g) * LD + e);
        acc.x += p.x; acc.y += p.y; acc.z += p.z; acc.w += p.w;
    }
    int col = e & (D - 1);
    const float* b = g ? bov : bom;
    acc.x += b[col]; acc.y += b[col + 1]; acc.z += b[col + 2]; acc.w += b[col + 3];
    if (g) {
        acc.x = softplusf(acc.x); acc.y = softplusf(acc.y);
        acc.z = softplusf(acc.z); acc.w = softplusf(acc.w);
    }
    *(float4*)(out + g * LD + e) = acc;
}

// ---------------- launch ----------------
extern "C" void kernel_launch(void* const* d_in, const int* in_sizes, int n_in,
                              void* d_out, int out_size)
{
    const float* mu  = (const float*)d_in[0];
    const float* var = (const float*)d_in[1];
    const float* wqm = (const float*)d_in[2],  * bqm = (const float*)d_in[3];
    const float* wqv = (const float*)d_in[4],  * bqv = (const float*)d_in[5];
    const float* wkm = (const float*)d_in[6],  * bkm = (const float*)d_in[7];
    const float* wkv = (const float*)d_in[8],  * bkv = (const float*)d_in[9];
    const float* wvm = (const float*)d_in[10], * bvm = (const float*)d_in[11];
    const float* wvv = (const float*)d_in[12], * bvv = (const float*)d_in[13];
    const float* wom = (const float*)d_in[14], * bom = (const float*)d_in[15];
    const float* wov = (const float*)d_in[16], * bov = (const float*)d_in[17];
    float* out = (float*)d_out;

    cudaFuncSetAttribute(attn_kernel, cudaFuncAttributeMaxDynamicSharedMemorySize,
                         ATTN_SMEM_FLOATS * 4);

    qkv_gemm_kernel<<<dim3(8, 2, 18), 256>>>(mu, var, wqm, wqv, wkm, wkv, wvm, wvv);
    prep_kernel<<<512, 256>>>(bqm, bqv, bkm, bkv, bvm, bvv);
    attn_kernel<<<dim3(8, 16), 256, ATTN_SMEM_FLOATS * 4>>>();
    out_gemm_kernel<<<dim3(8, 2, 16), 256>>>(wom, wov);
    out_epilogue_kernel<<<dim3(256, 2), 256>>>(bom, bov, out);
}

// round 6
// speedup vs baseline: 2.0328x; 1.2581x over previous
#include <cuda_runtime.h>
#include <cuda_bf16.h>
#include <math.h>
#include <stdint.h>

#define L 256
#define D 1024
#define H 16
#define DH 64
#define LD (L*D)

// ---------------- device scratch (no allocations allowed) ----------------
__device__ __align__(16) __nv_bfloat16 g_WT_hi[8*D*D];   // transposed weights [mat][n][k]
__device__ __align__(16) __nv_bfloat16 g_WT_lo[8*D*D];
__device__ __align__(16) __nv_bfloat16 g_act_hi[2*LD];   // mu, var  [m][k]
__device__ __align__(16) __nv_bfloat16 g_act_lo[2*LD];
__device__ __align__(16) __nv_bfloat16 g_O_hi[2*LD];     // Om, Ov bf16 splits (from attn)
__device__ __align__(16) __nv_bfloat16 g_O_lo[2*LD];
__device__ float g_qkv_part[2*6*LD];   // [ksplit][gemm][L*D]
__device__ float g_out_part[4*2*LD];   // [ksplit][gemm][L*D]
__device__ float g_Qm[LD], g_A[LD], g_F1[LD], g_F2[LD], g_Vm[LD], g_Vv[LD];
__device__ float g_Ck[H*L];

// ---------------- helpers ----------------
__device__ __forceinline__ uint32_t smem_u32(const void* p) {
    uint32_t a;
    asm("{ .reg .u64 t; cvta.to.shared.u64 t, %1; cvt.u32.u64 %0, t; }" : "=r"(a) : "l"(p));
    return a;
}
__device__ __forceinline__ void ldsm_x4(uint32_t (&r)[4], uint32_t addr) {
    asm volatile("ldmatrix.sync.aligned.m8n8.x4.shared.b16 {%0,%1,%2,%3}, [%4];"
                 : "=r"(r[0]), "=r"(r[1]), "=r"(r[2]), "=r"(r[3]) : "r"(addr));
}
__device__ __forceinline__ void mma_bf16(float (&d)[4], const uint32_t (&a)[4],
                                         uint32_t b0, uint32_t b1) {
    asm volatile(
        "mma.sync.aligned.m16n8k16.row.col.f32.bf16.bf16.f32 "
        "{%0,%1,%2,%3}, {%4,%5,%6,%7}, {%8,%9}, {%0,%1,%2,%3};"
        : "+f"(d[0]), "+f"(d[1]), "+f"(d[2]), "+f"(d[3])
        : "r"(a[0]), "r"(a[1]), "r"(a[2]), "r"(a[3]), "r"(b0), "r"(b1));
}
__device__ __forceinline__ float softplusf(float x) {
    return fmaxf(x, 0.0f) + log1pf(expf(-fabsf(x)));
}

// ---------------- HMMA bf16x3 GEMM ----------------
// Cpart[m0.., n0..] = sum_k act[m][k] * WT[n][k]  (3-product bf16 split)
// CTA tile 128m x 64n, BK=32, 8 warps (4m x 2n), warp 32x32.
#define BK 32
#define PITCH 40                      // halves per smem row (80B, LDSM conflict-free)
#define S_AHI 0
#define S_ALO (128*PITCH)             // 5120
#define S_BHI (2*128*PITCH)           // 10240
#define S_BLO (2*128*PITCH + 64*PITCH)// 12800
#define STAGE_H (2*128*PITCH + 2*64*PITCH)  // 15360 halves
#define GEMM_SMEM_B (2*STAGE_H*2)     // 61440 bytes

__device__ void gemm_mma(const __nv_bfloat16* __restrict__ wt_hi,
                         const __nv_bfloat16* __restrict__ wt_lo,
                         const __nv_bfloat16* __restrict__ a_hi,
                         const __nv_bfloat16* __restrict__ a_lo,
                         float* __restrict__ Cpart,
                         int m0, int n0, int k0, int nchunks)
{
    extern __shared__ __nv_bfloat16 sh[];
    const uint32_t sbase = smem_u32(sh);
    const int tid  = threadIdx.x;
    const int lane = tid & 31;
    const int wid  = tid >> 5;
    const int wm   = wid & 3;          // 0..3  (m-warp, 32 rows each)
    const int wn   = wid >> 2;         // 0..1  (n-warp, 32 cols each)

    float acc[2][4][4];
    #pragma unroll
    for (int mt = 0; mt < 2; mt++)
        #pragma unroll
        for (int nt = 0; nt < 4; nt++)
            #pragma unroll
            for (int r = 0; r < 4; r++) acc[mt][nt][r] = 0.0f;

    // per-thread load indices
    const int arow = tid >> 2;               // 0..63 (x2 passes covers 128)
    const int ac8  = (tid & 3) << 3;         // k offset in halves (0,8,16,24)
    uint4 ra_hi[2], ra_lo[2], rb_hi, rb_lo;

    auto LDG = [&](int c) {
        const int kg = k0 + c * BK;
        #pragma unroll
        for (int u = 0; u < 2; u++) {
            const size_t off = (size_t)(m0 + arow + u * 64) * D + kg + ac8;
            ra_hi[u] = *(const uint4*)(a_hi + off);
            ra_lo[u] = *(const uint4*)(a_lo + off);
        }
        const size_t boff = (size_t)(n0 + arow) * D + kg + ac8;
        rb_hi = *(const uint4*)(wt_hi + boff);
        rb_lo = *(const uint4*)(wt_lo + boff);
    };
    auto STS = [&](int buf) {
        __nv_bfloat16* s = sh + buf * STAGE_H;
        #pragma unroll
        for (int u = 0; u < 2; u++) {
            const int off = (arow + u * 64) * PITCH + ac8;
            *(uint4*)(s + S_AHI + off) = ra_hi[u];
            *(uint4*)(s + S_ALO + off) = ra_lo[u];
        }
        const int boff = arow * PITCH + ac8;
        *(uint4*)(s + S_BHI + boff) = rb_hi;
        *(uint4*)(s + S_BLO + boff) = rb_lo;
    };

    // precomputed LDSM lane addressing (byte offsets)
    const uint32_t a_lrow = (uint32_t)(wm * 32 + (lane & 15)) * PITCH;
    const uint32_t a_koff = (uint32_t)((lane >> 4) << 3);
    const uint32_t b_lrow = (uint32_t)(wn * 32 + ((lane >> 4) << 3) + (lane & 7)) * PITCH;
    const uint32_t b_koff = (uint32_t)(((lane >> 3) & 1) << 3);

    LDG(0); STS(0); __syncthreads();
    for (int c = 0; c < nchunks; c++) {
        const int cur = c & 1;
        if (c + 1 < nchunks) LDG(c + 1);
        const uint32_t sb = sbase + (uint32_t)cur * (STAGE_H * 2);
        #pragma unroll
        for (int ks = 0; ks < 2; ks++) {
            uint32_t ahi[2][4], alo[2][4], bhi[2][4], blo[2][4];
            #pragma unroll
            for (int mt = 0; mt < 2; mt++) {
                uint32_t ad = sb + (S_AHI + a_lrow + mt * 16 * PITCH + ks * 16 + a_koff) * 2;
                ldsm_x4(ahi[mt], ad);
                ldsm_x4(alo[mt], ad + (S_ALO - S_AHI) * 2);
            }
            #pragma unroll
            for (int p = 0; p < 2; p++) {
                uint32_t bd = sb + (S_BHI + b_lrow + p * 16 * PITCH + ks * 16 + b_koff) * 2;
                ldsm_x4(bhi[p], bd);
                ldsm_x4(blo[p], bd + (S_BLO - S_BHI) * 2);
            }
            #pragma unroll
            for (int mt = 0; mt < 2; mt++)
                #pragma unroll
                for (int nt = 0; nt < 4; nt++) {
                    const int p = nt >> 1, q = (nt & 1) * 2;
                    mma_bf16(acc[mt][nt], ahi[mt], bhi[p][q], bhi[p][q + 1]);
                    mma_bf16(acc[mt][nt], ahi[mt], blo[p][q], blo[p][q + 1]);
                    mma_bf16(acc[mt][nt], alo[mt], bhi[p][q], bhi[p][q + 1]);
                }
        }
        if (c + 1 < nchunks) STS(cur ^ 1);
        __syncthreads();
    }

    // epilogue: write fp32 partials
    #pragma unroll
    for (int mt = 0; mt < 2; mt++)
        #pragma unroll
        for (int nt = 0; nt < 4; nt++) {
            const int r = m0 + wm * 32 + mt * 16 + (lane >> 2);
            const int cL = n0 + wn * 32 + nt * 8 + (lane & 3) * 2;
            *(float2*)(Cpart + (size_t)r * D + cL) =
                make_float2(acc[mt][nt][0], acc[mt][nt][1]);
            *(float2*)(Cpart + (size_t)(r + 8) * D + cL) =
                make_float2(acc[mt][nt][2], acc[mt][nt][3]);
        }
}

// QKV: 6 GEMMs, split-K 2 -> grid(16, 4, 6) = 384 CTAs
__global__ __launch_bounds__(256, 2) void qkv_gemm_mma()
{
    const int g = blockIdx.z;
    const int mt = blockIdx.y & 1, s = blockIdx.y >> 1;
    gemm_mma(g_WT_hi + (size_t)g * D * D, g_WT_lo + (size_t)g * D * D,
             g_act_hi + (size_t)(g & 1) * LD, g_act_lo + (size_t)(g & 1) * LD,
             g_qkv_part + (size_t)(s * 6 + g) * LD,
             mt * 128, blockIdx.x * 64, s * 512, 16);
}

// out: 2 GEMMs, split-K 4 -> grid(16, 8, 2) = 256 CTAs
__global__ __launch_bounds__(256, 2) void out_gemm_mma()
{
    const int g = blockIdx.z;
    const int mt = blockIdx.y & 1, s = blockIdx.y >> 1;
    gemm_mma(g_WT_hi + (size_t)(6 + g) * D * D, g_WT_lo + (size_t)(6 + g) * D * D,
             g_O_hi + (size_t)g * LD, g_O_lo + (size_t)g * LD,
             g_out_part + (size_t)(s * 2 + g) * LD,
             mt * 128, blockIdx.x * 64, s * 256, 8);
}

// ---------------- weight convert + transpose: W[k][n] -> WT{hi,lo}[n][k] ----
__global__ __launch_bounds__(256) void convert_w_kernel(
    const float* w0, const float* w1, const float* w2, const float* w3,
    const float* w4, const float* w5, const float* w6, const float* w7)
{
    __shared__ float tile[32][33];
    const float* W;
    switch (blockIdx.z) {
        case 0: W = w0; break; case 1: W = w1; break;
        case 2: W = w2; break; case 3: W = w3; break;
        case 4: W = w4; break; case 5: W = w5; break;
        case 6: W = w6; break; default: W = w7; break;
    }
    int kb = blockIdx.x * 32, nb = blockIdx.y * 32;
    int tx = threadIdx.x & 31, ty = threadIdx.x >> 5;
    #pragma unroll
    for (int i = 0; i < 4; i++)
        tile[ty * 4 + i][tx] = W[(size_t)(kb + ty * 4 + i) * D + nb + tx];
    __syncthreads();
    size_t base = (size_t)blockIdx.z * D * D;
    #pragma unroll
    for (int i = 0; i < 4; i++) {
        float v = tile[tx][ty * 4 + i];
        __nv_bfloat16 hi = __float2bfloat16(v);
        __nv_bfloat16 lo = __float2bfloat16(v - __bfloat162float(hi));
        size_t o = base + (size_t)(nb + ty * 4 + i) * D + kb + tx;
        g_WT_hi[o] = hi;
        g_WT_lo[o] = lo;
    }
}

// ---------------- activation convert: mu,var -> bf16 hi/lo ----------------
__global__ __launch_bounds__(256) void convert_act_kernel(const float* mu, const float* var)
{
    int t = blockIdx.x * 256 + threadIdx.x;
    int e = t * 4;
    const float* src = (e < LD) ? mu : var;
    float4 v = *(const float4*)(src + (e & (LD - 1)));
    float vv[4] = { v.x, v.y, v.z, v.w };
    union { __nv_bfloat16 h[4]; uint2 u; } Hi, Lo;
    #pragma unroll
    for (int i = 0; i < 4; i++) {
        Hi.h[i] = __float2bfloat16(vv[i]);
        Lo.h[i] = __float2bfloat16(vv[i] - __bfloat162float(Hi.h[i]));
    }
    *(uint2*)(g_act_hi + e) = Hi.u;
    *(uint2*)(g_act_lo + e) = Lo.u;
}

// ---------------- prep: split-sum(2) + bias + act + KL features -------------
__global__ __launch_bounds__(256) void prep_kernel(
    const float* bqm, const float* bqv, const float* bkm, const float* bkv,
    const float* bvm, const float* bvv)
{
    int tid = blockIdx.x * 256 + threadIdx.x;
    int e0  = tid * 2;
    float c = 0.0f;
    float2 v[6];
    #pragma unroll
    for (int g = 0; g < 6; g++) {
        float2 p0 = *(const float2*)(g_qkv_part + (size_t)(0 * 6 + g) * LD + e0);
        float2 p1 = *(const float2*)(g_qkv_part + (size_t)(1 * 6 + g) * LD + e0);
        v[g] = make_float2(p0.x + p1.x, p0.y + p1.y);
    }
    int col = e0 & (D - 1);
    float vals[6][2] = {
        { v[0].x + bqm[col], v[0].y + bqm[col + 1] },
        { v[1].x + bqv[col], v[1].y + bqv[col + 1] },
        { v[2].x + bkm[col], v[2].y + bkm[col + 1] },
        { v[3].x + bkv[col], v[3].y + bkv[col + 1] },
        { v[4].x + bvm[col], v[4].y + bvm[col + 1] },
        { v[5].x + bvv[col], v[5].y + bvv[col + 1] },
    };
    float qm2[2], a2v[2], f1v[2], f2v[2], vv2[2];
    #pragma unroll
    for (int u = 0; u < 2; u++) {
        float qm = vals[0][u];
        float qv = softplusf(vals[1][u]);
        float km = vals[2][u];
        float kv = softplusf(vals[3][u]);
        float inv = 1.0f / kv;
        qm2[u] = qm;
        a2v[u] = 0.5f * (qm * qm + qv);
        f1v[u] = inv;
        f2v[u] = km * inv;
        vv2[u] = softplusf(vals[5][u]);
        c += 0.5f * (km * km * inv + logf(kv));
    }
    *(float2*)(g_Qm + e0) = make_float2(qm2[0], qm2[1]);
    *(float2*)(g_A  + e0) = make_float2(a2v[0], a2v[1]);
    *(float2*)(g_F1 + e0) = make_float2(f1v[0], f1v[1]);
    *(float2*)(g_F2 + e0) = make_float2(f2v[0], f2v[1]);
    *(float2*)(g_Vm + e0) = make_float2(vals[4][0], vals[4][1]);
    *(float2*)(g_Vv + e0) = make_float2(vv2[0], vv2[1]);

    #pragma unroll
    for (int off = 16; off; off >>= 1) c += __shfl_xor_sync(0xffffffffu, c, off);
    if ((threadIdx.x & 31) == 0) {
        int w = tid >> 5;
        int row = w >> 4, h = w & 15;
        g_Ck[h * L + row] = c;
    }
}

// ---------------- fused attention per (q-tile-32, head) ----------------
#define ATTN_SMEM_FLOATS 37376
#define O_AQ 0
#define O_QM 2112
#define O_F1 4224
#define O_F2 20672
#define O_CK 37120
#define O_VM 0
#define O_VV 4096
#define O_P  8192
#define O_P2 16640

__global__ __launch_bounds__(256) void attn_kernel()
{
    extern __shared__ float sm[];
    const int h  = blockIdx.y;
    const int q0 = blockIdx.x * 32;
    const int tid = threadIdx.x;
    const int tx = tid & 15, ty = tid >> 4;

    #pragma unroll
    for (int u = 0; u < 2; u++) {
        int idx = tid + u * 256;
        int q = idx >> 4, d4 = (idx & 15) << 2;
        float4 a = *(const float4*)(g_A  + (q0 + q) * D + h * DH + d4);
        float4 m = *(const float4*)(g_Qm + (q0 + q) * D + h * DH + d4);
        sm[O_AQ + (d4 + 0) * 33 + q] = a.x;
        sm[O_AQ + (d4 + 1) * 33 + q] = a.y;
        sm[O_AQ + (d4 + 2) * 33 + q] = a.z;
        sm[O_AQ + (d4 + 3) * 33 + q] = a.w;
        sm[O_QM + (d4 + 0) * 33 + q] = -m.x;
        sm[O_QM + (d4 + 1) * 33 + q] = -m.y;
        sm[O_QM + (d4 + 2) * 33 + q] = -m.z;
        sm[O_QM + (d4 + 3) * 33 + q] = -m.w;
    }
    #pragma unroll
    for (int u = 0; u < 16; u++) {
        int idx = tid + u * 256;
        int k = idx >> 4, d4 = (idx & 15) << 2;
        float4 f1 = *(const float4*)(g_F1 + k * D + h * DH + d4);
        float4 f2 = *(const float4*)(g_F2 + k * D + h * DH + d4);
        sm[O_F1 + (d4 + 0) * 257 + k] = f1.x;
        sm[O_F1 + (d4 + 1) * 257 + k] = f1.y;
        sm[O_F1 + (d4 + 2) * 257 + k] = f1.z;
        sm[O_F1 + (d4 + 3) * 257 + k] = f1.w;
        sm[O_F2 + (d4 + 0) * 257 + k] = f2.x;
        sm[O_F2 + (d4 + 1) * 257 + k] = f2.y;
        sm[O_F2 + (d4 + 2) * 257 + k] = f2.z;
        sm[O_F2 + (d4 + 3) * 257 + k] = f2.w;
    }
    if (tid < 256) sm[O_CK + tid] = g_Ck[h * L + tid];
    __syncthreads();

    float s[2][16];
    #pragma unroll
    for (int i = 0; i < 2; i++)
        #pragma unroll
        for (int j = 0; j < 16; j++) s[i][j] = 0.0f;

    #pragma unroll 4
    for (int d = 0; d < 64; d++) {
        float a[2], qn[2];
        #pragma unroll
        for (int i = 0; i < 2; i++) {
            a[i]  = sm[O_AQ + d * 33 + ty * 2 + i];
            qn[i] = sm[O_QM + d * 33 + ty * 2 + i];
        }
        #pragma unroll
        for (int j = 0; j < 16; j++) {
            float f1 = sm[O_F1 + d * 257 + j * 16 + tx];
            float f2 = sm[O_F2 + d * 257 + j * 16 + tx];
            #pragma unroll
            for (int i = 0; i < 2; i++)
                s[i][j] += a[i] * f1 + qn[i] * f2;
        }
    }

    #pragma unroll
    for (int j = 0; j < 16; j++) {
        float ck = sm[O_CK + j * 16 + tx];
        #pragma unroll
        for (int i = 0; i < 2; i++)
            s[i][j] = -0.125f * (s[i][j] + ck);
    }

    float rinv[2];
    #pragma unroll
    for (int i = 0; i < 2; i++) {
        float m = s[i][0];
        #pragma unroll
        for (int j = 1; j < 16; j++) m = fmaxf(m, s[i][j]);
        #pragma unroll
        for (int off = 8; off; off >>= 1)
            m = fmaxf(m, __shfl_xor_sync(0xffffffffu, m, off));
        float sum = 0.0f;
        #pragma unroll
        for (int j = 0; j < 16; j++) {
            float e = __expf(s[i][j] - m);
            s[i][j] = e;
            sum += e;
        }
        #pragma unroll
        for (int off = 8; off; off >>= 1)
            sum += __shfl_xor_sync(0xffffffffu, sum, off);
        rinv[i] = 1.0f / sum;
    }

    __syncthreads();

    #pragma unroll
    for (int j = 0; j < 16; j++) {
        int k = j * 16 + tx;
        #pragma unroll
        for (int i = 0; i < 2; i++) {
            int q = ty * 2 + i;
            float pn = s[i][j] * rinv[i];
            sm[O_P  + k * 33 + q] = pn;
            sm[O_P2 + k * 33 + q] = pn * pn;
        }
    }

    float om[2][4], ov[2][4];
    #pragma unroll
    for (int i = 0; i < 2; i++)
        #pragma unroll
        for (int r = 0; r < 4; r++) { om[i][r] = 0.0f; ov[i][r] = 0.0f; }

    for (int kb = 0; kb < 4; kb++) {
        #pragma unroll
        for (int u = 0; u < 4; u++) {
            int idx = tid + u * 256;
            int r = idx >> 4, d4 = (idx & 15) << 2;
            *(float4*)&sm[O_VM + r * 64 + d4] =
                *(const float4*)(g_Vm + (kb * 64 + r) * D + h * DH + d4);
            *(float4*)&sm[O_VV + r * 64 + d4] =
                *(const float4*)(g_Vv + (kb * 64 + r) * D + h * DH + d4);
        }
        __syncthreads();
        #pragma unroll 4
        for (int kk = 0; kk < 64; kk++) {
            int k = kb * 64 + kk;
            float pm[2], pv[2];
            #pragma unroll
            for (int i = 0; i < 2; i++) {
                pm[i] = sm[O_P  + k * 33 + ty * 2 + i];
                pv[i] = sm[O_P2 + k * 33 + ty * 2 + i];
            }
            float4 vm = *(const float4*)&sm[O_VM + kk * 64 + tx * 4];
            float4 vv = *(const float4*)&sm[O_VV + kk * 64 + tx * 4];
            #pragma unroll
            for (int i = 0; i < 2; i++) {
                om[i][0] += pm[i] * vm.x; om[i][1] += pm[i] * vm.y;
                om[i][2] += pm[i] * vm.z; om[i][3] += pm[i] * vm.w;
                ov[i][0] += pv[i] * vv.x; ov[i][1] += pv[i] * vv.y;
                ov[i][2] += pv[i] * vv.z; ov[i][3] += pv[i] * vv.w;
            }
        }
        if (kb < 3) __syncthreads();
    }

    // store Om/Ov as bf16 hi/lo splits for the HMMA out-GEMM
    #pragma unroll
    for (int i = 0; i < 2; i++) {
        int q = q0 + ty * 2 + i;
        size_t base = (size_t)q * D + h * DH + tx * 4;
        union { __nv_bfloat16 h[4]; uint2 u; } Hi, Lo;
        #pragma unroll
        for (int r = 0; r < 4; r++) {
            Hi.h[r] = __float2bfloat16(om[i][r]);
            Lo.h[r] = __float2bfloat16(om[i][r] - __bfloat162float(Hi.h[r]));
        }
        *(uint2*)(g_O_hi + base) = Hi.u;
        *(uint2*)(g_O_lo + base) = Lo.u;
        #pragma unroll
        for (int r = 0; r < 4; r++) {
            Hi.h[r] = __float2bfloat16(ov[i][r]);
            Lo.h[r] = __float2bfloat16(ov[i][r] - __bfloat162float(Hi.h[r]));
        }
        *(uint2*)(g_O_hi + LD + base) = Hi.u;
        *(uint2*)(g_O_lo + LD + base) = Lo.u;
    }
}

// ---------------- output epilogue: sum 4 splits + bias + softplus ----------
__global__ __launch_bounds__(256) void out_epilogue_kernel(
    const float* bom, const float* bov, float* out)
{
    int g = blockIdx.y;
    int e = (blockIdx.x * 256 + threadIdx.x) * 4;
    float4 acc = make_float4(0.f, 0.f, 0.f, 0.f);
    #pragma unroll
    for (int s = 0; s < 4; s++) {
        float4 p = *(const float4*)(g_out_part + (size_t)(s * 2 + g) * LD + e);
        acc.x += p.x; acc.y += p.y; acc.z += p.z; acc.w += p.w;
    }
    int col = e & (D - 1);
    const float* b = g ? bov : bom;
    acc.x += b[col]; acc.y += b[col + 1]; acc.z += b[col + 2]; acc.w += b[col + 3];
    if (g) {
        acc.x = softplusf(acc.x); acc.y = softplusf(acc.y);
        acc.z = softplusf(acc.z); acc.w = softplusf(acc.w);
    }
    *(float4*)(out + (size_t)g * LD + e) = acc;
}

// ---------------- launch ----------------
extern "C" void kernel_launch(void* const* d_in, const int* in_sizes, int n_in,
                              void* d_out, int out_size)
{
    const float* mu  = (const float*)d_in[0];
    const float* var = (const float*)d_in[1];
    const float* wqm = (const float*)d_in[2],  * bqm = (const float*)d_in[3];
    const float* wqv = (const float*)d_in[4],  * bqv = (const float*)d_in[5];
    const float* wkm = (const float*)d_in[6],  * bkm = (const float*)d_in[7];
    const float* wkv = (const float*)d_in[8],  * bkv = (const float*)d_in[9];
    const float* wvm = (const float*)d_in[10], * bvm = (const float*)d_in[11];
    const float* wvv = (const float*)d_in[12], * bvv = (const float*)d_in[13];
    const float* wom = (const float*)d_in[14], * bom = (const float*)d_in[15];
    const float* wov = (const float*)d_in[16], * bov = (const float*)d_in[17];
    float* out = (float*)d_out;

    cudaFuncSetAttribute(qkv_gemm_mma, cudaFuncAttributeMaxDynamicSharedMemorySize, GEMM_SMEM_B);
    cudaFuncSetAttribute(out_gemm_mma, cudaFuncAttributeMaxDynamicSharedMemorySize, GEMM_SMEM_B);
    cudaFuncSetAttribute(attn_kernel, cudaFuncAttributeMaxDynamicSharedMemorySize,
                         ATTN_SMEM_FLOATS * 4);

    convert_w_kernel<<<dim3(32, 32, 8), 256>>>(wqm, wqv, wkm, wkv, wvm, wvv, wom, wov);
    convert_act_kernel<<<512, 256>>>(mu, var);
    qkv_gemm_mma<<<dim3(16, 4, 6), 256, GEMM_SMEM_B>>>();
    prep_kernel<<<512, 256>>>(bqm, bqv, bkm, bkv, bvm, bvv);
    attn_kernel<<<dim3(8, 16), 256, ATTN_SMEM_FLOATS * 4>>>();
    out_gemm_mma<<<dim3(16, 8, 2), 256, GEMM_SMEM_B>>>();
    out_epilogue_kernel<<<dim3(256, 2), 256>>>(bom, bov, out);
}